// round 1
// baseline (speedup 1.0000x reference)
#include <cuda_runtime.h>

// FastFood layer: out[row, r*1024 + j] = (FWHT( FWHT(x[row]*B[r])[P[r]] * G[r] ))[j] * S[r,j] / 32
// D = 1024, R = 4, M = 16384 rows.
//
// One warp per row. Element layout inside a warp: register k, lane l <-> index k*32 + l.
// FWHT_1024 = H32 (lane bits, via shfl_xor) (x) H32 (register bits, in-register butterflies).
// Permutation gather goes through a per-warp 4KB shared scratch.

#define FF_D 1024
#define FF_R 4
#define WARPS_PER_BLOCK 8
#define THREADS (WARPS_PER_BLOCK * 32)

__device__ __forceinline__ void fwht1024(float v[32], int lane) {
    // Stages over the 5 lane bits (index bits 0..4)
    #pragma unroll
    for (int m = 1; m <= 16; m <<= 1) {
        const bool upper = (lane & m) != 0;
        #pragma unroll
        for (int k = 0; k < 32; k++) {
            float w = __shfl_xor_sync(0xffffffffu, v[k], m);
            v[k] = upper ? (w - v[k]) : (v[k] + w);
        }
    }
    // Stages over the 5 register bits (index bits 5..9)
    #pragma unroll
    for (int m = 1; m <= 16; m <<= 1) {
        #pragma unroll
        for (int k = 0; k < 32; k++) {
            if ((k & m) == 0) {
                float a = v[k];
                float b = v[k | m];
                v[k]     = a + b;
                v[k | m] = a - b;
            }
        }
    }
}

__global__ __launch_bounds__(THREADS)
void fastfood_kernel(const float* __restrict__ x,
                     const float* __restrict__ B,
                     const float* __restrict__ G,
                     const float* __restrict__ S,
                     const int*   __restrict__ P,
                     float* __restrict__ out,
                     int M)
{
    __shared__ float scratch[WARPS_PER_BLOCK][FF_D];

    const int warp = threadIdx.x >> 5;
    const int lane = threadIdx.x & 31;
    const int row  = blockIdx.x * WARPS_PER_BLOCK + warp;
    if (row >= M) return;

    // Load the row once, keep it in registers across all R transforms.
    float xv[32];
    const float* xr = x + (size_t)row * FF_D;
    #pragma unroll
    for (int k = 0; k < 32; k++) xv[k] = xr[k * 32 + lane];

    float* sm = scratch[warp];

    #pragma unroll 1
    for (int r = 0; r < FF_R; r++) {
        const float* Br = B + r * FF_D;
        const float* Gr = G + r * FF_D;
        const float* Sr = S + r * FF_D;
        const int*   Pr = P + r * FF_D;

        float v[32];
        #pragma unroll
        for (int k = 0; k < 32; k++) v[k] = xv[k] * __ldg(&Br[k * 32 + lane]);

        fwht1024(v, lane);

        // Permutation gather through shared memory (per-warp private scratch).
        #pragma unroll
        for (int k = 0; k < 32; k++) sm[k * 32 + lane] = v[k];
        __syncwarp();

        #pragma unroll
        for (int k = 0; k < 32; k++) {
            int j = k * 32 + lane;
            v[k] = sm[__ldg(&Pr[j])] * __ldg(&Gr[j]);
        }
        __syncwarp();  // all gathers done before scratch is overwritten next iter

        fwht1024(v, lane);

        float* o = out + (size_t)row * (FF_R * FF_D) + r * FF_D;
        #pragma unroll
        for (int k = 0; k < 32; k++) {
            int j = k * 32 + lane;
            o[j] = v[k] * __ldg(&Sr[j]) * 0.03125f;  // 1/sqrt(1024)
        }
    }
}

extern "C" void kernel_launch(void* const* d_in, const int* in_sizes, int n_in,
                              void* d_out, int out_size) {
    const float* x = (const float*)d_in[0];   // (4,512,8,1024) fp32
    const float* B = (const float*)d_in[1];   // (4,1024) fp32
    const float* G = (const float*)d_in[2];   // (4,1024) fp32
    const float* S = (const float*)d_in[3];   // (4,1024) fp32
    const int*   P = (const int*)  d_in[4];   // (4,1024) int32
    float* out = (float*)d_out;

    const int M = in_sizes[0] / FF_D;         // 16384 rows
    const int blocks = (M + WARPS_PER_BLOCK - 1) / WARPS_PER_BLOCK;
    fastfood_kernel<<<blocks, THREADS>>>(x, B, G, S, P, out, M);
}